// round 9
// baseline (speedup 1.0000x reference)
#include <cuda_runtime.h>
#include <cstdint>

// ----------------------------------------------------------------------------
// Fused sparse conv on the tensor pipe, PERSISTENT-TILE version.
// Block = one offset k, loops over tiles of 128 compacted pairs:
//   W_in[k] hi/lo staged in smem ONCE per block, then per tile:
//   gather x -> hi/lo tf32 planes -> mma.sync.m16n8k8 (3xTF32, fp32 acc)
//   -> stage C -> red.global.add.v4 scatter.
// ----------------------------------------------------------------------------

constexpr int CIN   = 32;
constexpr int CMID  = 64;
constexpr int COUT  = 32;
constexpr int MAXN  = 200192;
constexpr int MAXK  = 27;
constexpr int MAXP  = 400000;
constexpr int PT    = 128;       // pairs per tile

// smem strides (floats) for conflict-free fragment access:
constexpr int SX1 = 36;
constexpr int SW1 = 72;
constexpr int SO1 = 68;
constexpr int SX2 = 68;
constexpr int SW2 = 40;
constexpr int SO2 = 36;

constexpr int POOL1 = 2 * PT * SX1 + 2 * CIN  * SW1;   // 13824 floats (54 KB)
constexpr int POOL2 = 2 * PT * SX2 + 2 * CMID * SW2;   // 22528 floats (88 KB)

__device__ float g_h[(size_t)MAXN * CMID];
__device__ uint2 g_pairs[(size_t)MAXK * MAXP];
__device__ int   g_cnt[MAXK];

static __device__ __forceinline__ unsigned f2tf(float x) {
    unsigned r; asm("cvt.rna.tf32.f32 %0, %1;" : "=r"(r) : "f"(x)); return r;
}
static __device__ __forceinline__ void mma_tf32(
    float4& c, unsigned a0, unsigned a1, unsigned a2, unsigned a3,
    unsigned b0, unsigned b1)
{
    asm volatile(
        "mma.sync.aligned.m16n8k8.row.col.f32.tf32.tf32.f32 "
        "{%0,%1,%2,%3}, {%4,%5,%6,%7}, {%8,%9}, {%0,%1,%2,%3};"
        : "+f"(c.x), "+f"(c.y), "+f"(c.z), "+f"(c.w)
        : "r"(a0), "r"(a1), "r"(a2), "r"(a3), "r"(b0), "r"(b1));
}
static __device__ __forceinline__ void red_add_v4(float* p, float4 v) {
    asm volatile("red.global.add.v4.f32 [%0], {%1, %2, %3, %4};"
                 :: "l"(p), "f"(v.x), "f"(v.y), "f"(v.z), "f"(v.w) : "memory");
}
static __device__ __forceinline__ void hilo(float x, float& h, float& l) {
    h = __uint_as_float(f2tf(x));
    l = __uint_as_float(f2tf(x - h));
}

// ---------------------------------------------------------------------------
__global__ void zero_kernel(float4* __restrict__ out, int n_out4, int n_h4) {
    int i = blockIdx.x * blockDim.x + threadIdx.x;
    float4 z = make_float4(0.f, 0.f, 0.f, 0.f);
    if (i < n_out4) out[i] = z;
    if (i < n_h4) reinterpret_cast<float4*>(g_h)[i] = z;
    if (i < MAXK) g_cnt[i] = 0;
}

// ---------------------------------------------------------------------------
__global__ __launch_bounds__(256) void compact_kernel(
    const int* __restrict__ in_idx, const int* __restrict__ out_idx,
    const float* __restrict__ mask, int P)
{
    const int k = blockIdx.y;
    const int p = blockIdx.x * blockDim.x + threadIdx.x;
    bool v = false; int vin = 0, vout = 0;
    if (p < P) {
        size_t o = (size_t)k * P + p;
        v = mask[o] > 0.5f;
        if (v) { vin = in_idx[o]; vout = out_idx[o]; }
    }
    unsigned b = __ballot_sync(0xffffffffu, v);
    int cnt = __popc(b);
    if (cnt == 0) return;
    const int lane = threadIdx.x & 31;
    const int leader = __ffs(b) - 1;
    int base = 0;
    if (lane == leader) base = atomicAdd(&g_cnt[k], cnt);
    base = __shfl_sync(0xffffffffu, base, leader);
    if (v) {
        int off = __popc(b & ((1u << lane) - 1u));
        g_pairs[(size_t)k * MAXP + base + off] =
            make_uint2((unsigned)vin, (unsigned)vout);
    }
}

// ---------------------------------------------------------------------------
// Fused layer 1 (persistent): g_h[vout][0:64] += feats[vin][0:32] @ W_in[k]
// ---------------------------------------------------------------------------
__global__ __launch_bounds__(256) void fused1_kernel(
    const float* __restrict__ feats, const float* __restrict__ W_in)
{
    const int k      = blockIdx.y;
    const int cnt    = g_cnt[k];
    const int ntiles = (cnt + PT - 1) / PT;
    const int t      = threadIdx.x;
    const int lane   = t & 31;
    const int wrp    = t >> 5;

    extern __shared__ float pool[];
    float* sxh = pool;                     // [PT][SX1]
    float* sxl = pool + PT * SX1;
    float* swh = pool + 2 * PT * SX1;      // [CIN][SW1]
    float* swl = swh + CIN * SW1;
    float* so  = pool;                     // aliases x planes: [PT][SO1]
    __shared__ uint2 sp[PT];

    // Stage W hi/lo ONCE per block.
    for (int i = t; i < CIN * CMID; i += 256) {
        int c = i >> 6, d = i & 63;
        float h, l; hilo(W_in[(size_t)k * CIN * CMID + i], h, l);
        swh[c * SW1 + d] = h; swl[c * SW1 + d] = l;
    }

    const int gid = lane >> 2, tig = lane & 3;
    const int r0  = 16 * wrp + gid;

    for (int tile = blockIdx.x; tile < ntiles; tile += gridDim.x) {
        const int base = tile * PT;
        const int nv   = min(PT, cnt - base);

        __syncthreads();   // prev red done reading so / W staged (first iter)
        if (t < PT) sp[t] = (t < nv) ? g_pairs[(size_t)k * MAXP + base + t]
                                     : make_uint2(0u, 0u);
        __syncthreads();

        // Gather 128 rows x 32 floats (8 lanes per 128B row), hi/lo convert.
        for (int i = t; i < PT * 8; i += 256) {
            const int r = i >> 3, q = i & 7;
            float4 v = reinterpret_cast<const float4*>(feats + (size_t)sp[r].x * CIN)[q];
            float* dh = sxh + r * SX1 + q * 4;
            float* dl = sxl + r * SX1 + q * 4;
            hilo(v.x, dh[0], dl[0]); hilo(v.y, dh[1], dl[1]);
            hilo(v.z, dh[2], dl[2]); hilo(v.w, dh[3], dl[3]);
        }
        __syncthreads();

        float4 acc[8];
#pragma unroll
        for (int nt = 0; nt < 8; nt++) acc[nt] = make_float4(0.f, 0.f, 0.f, 0.f);

#pragma unroll
        for (int ks = 0; ks < 4; ks++) {
            const int ka = ks * 8;
            const float* ph = sxh + r0 * SX1 + ka;
            const float* pl = sxl + r0 * SX1 + ka;
            unsigned ah0 = __float_as_uint(ph[tig]);
            unsigned ah1 = __float_as_uint(ph[8 * SX1 + tig]);
            unsigned ah2 = __float_as_uint(ph[tig + 4]);
            unsigned ah3 = __float_as_uint(ph[8 * SX1 + tig + 4]);
            unsigned al0 = __float_as_uint(pl[tig]);
            unsigned al1 = __float_as_uint(pl[8 * SX1 + tig]);
            unsigned al2 = __float_as_uint(pl[tig + 4]);
            unsigned al3 = __float_as_uint(pl[8 * SX1 + tig + 4]);
#pragma unroll
            for (int nt = 0; nt < 8; nt++) {
                const int nc = nt * 8 + gid;
                unsigned bh0 = __float_as_uint(swh[(ka + tig) * SW1 + nc]);
                unsigned bh1 = __float_as_uint(swh[(ka + tig + 4) * SW1 + nc]);
                unsigned bl0 = __float_as_uint(swl[(ka + tig) * SW1 + nc]);
                unsigned bl1 = __float_as_uint(swl[(ka + tig + 4) * SW1 + nc]);
                mma_tf32(acc[nt], ah0, ah1, ah2, ah3, bh0, bh1);
                mma_tf32(acc[nt], ah0, ah1, ah2, ah3, bl0, bl1);
                mma_tf32(acc[nt], al0, al1, al2, al3, bh0, bh1);
            }
        }

        __syncthreads();   // done reading x planes
#pragma unroll
        for (int nt = 0; nt < 8; nt++) {
            const int cc = nt * 8 + 2 * tig;
            *reinterpret_cast<float2*>(so + r0 * SO1 + cc)       = make_float2(acc[nt].x, acc[nt].y);
            *reinterpret_cast<float2*>(so + (r0 + 8) * SO1 + cc) = make_float2(acc[nt].z, acc[nt].w);
        }
        __syncthreads();

        for (int i = t; i < PT * 16; i += 256) {
            const int r = i >> 4, l = i & 15;
            if (r < nv)
                red_add_v4(g_h + (size_t)sp[r].y * CMID + l * 4,
                           *reinterpret_cast<float4*>(so + r * SO1 + l * 4));
        }
    }
}

// ---------------------------------------------------------------------------
// Fused layer 2 (persistent): out[vout][0:32] += relu(g_h[vin][0:64]) @ W_out[k]
// ---------------------------------------------------------------------------
__global__ __launch_bounds__(256) void fused2_kernel(
    const float* __restrict__ W_out, float* __restrict__ out)
{
    const int k      = blockIdx.y;
    const int cnt    = g_cnt[k];
    const int ntiles = (cnt + PT - 1) / PT;
    const int t      = threadIdx.x;
    const int lane   = t & 31;
    const int wrp    = t >> 5;

    extern __shared__ float pool[];
    float* sxh = pool;                     // [PT][SX2]
    float* sxl = pool + PT * SX2;
    float* swh = pool + 2 * PT * SX2;      // [CMID][SW2]
    float* swl = swh + CMID * SW2;
    float* so  = pool;                     // aliases x planes: [PT][SO2]
    __shared__ uint2 sp[PT];

    for (int i = t; i < CMID * COUT; i += 256) {
        int c = i >> 5, d = i & 31;
        float h, l; hilo(W_out[(size_t)k * CMID * COUT + i], h, l);
        swh[c * SW2 + d] = h; swl[c * SW2 + d] = l;
    }

    const int gid = lane >> 2, tig = lane & 3;
    const int r0  = 16 * wrp + gid;

    for (int tile = blockIdx.x; tile < ntiles; tile += gridDim.x) {
        const int base = tile * PT;
        const int nv   = min(PT, cnt - base);

        __syncthreads();
        if (t < PT) sp[t] = (t < nv) ? g_pairs[(size_t)k * MAXP + base + t]
                                     : make_uint2(0u, 0u);
        __syncthreads();

        // Gather 128 rows x 64 floats (16 lanes per 256B row), ReLU + hi/lo.
        for (int i = t; i < PT * 16; i += 256) {
            const int r = i >> 4, q = i & 15;
            float4 v = reinterpret_cast<const float4*>(g_h + (size_t)sp[r].x * CMID)[q];
            float* dh = sxh + r * SX2 + q * 4;
            float* dl = sxl + r * SX2 + q * 4;
            hilo(fmaxf(v.x, 0.f), dh[0], dl[0]); hilo(fmaxf(v.y, 0.f), dh[1], dl[1]);
            hilo(fmaxf(v.z, 0.f), dh[2], dl[2]); hilo(fmaxf(v.w, 0.f), dh[3], dl[3]);
        }
        __syncthreads();

        float4 acc[4];
#pragma unroll
        for (int nt = 0; nt < 4; nt++) acc[nt] = make_float4(0.f, 0.f, 0.f, 0.f);

#pragma unroll
        for (int ks = 0; ks < 8; ks++) {
            const int ka = ks * 8;
            const float* ph = sxh + r0 * SX2 + ka;
            const float* pl = sxl + r0 * SX2 + ka;
            unsigned ah0 = __float_as_uint(ph[tig]);
            unsigned ah1 = __float_as_uint(ph[8 * SX2 + tig]);
            unsigned ah2 = __float_as_uint(ph[tig + 4]);
            unsigned ah3 = __float_as_uint(ph[8 * SX2 + tig + 4]);
            unsigned al0 = __float_as_uint(pl[tig]);
            unsigned al1 = __float_as_uint(pl[8 * SX2 + tig]);
            unsigned al2 = __float_as_uint(pl[tig + 4]);
            unsigned al3 = __float_as_uint(pl[8 * SX2 + tig + 4]);
#pragma unroll
            for (int nt = 0; nt < 4; nt++) {
                const int nc = nt * 8 + gid;
                unsigned bh0 = __float_as_uint(swh[(ka + tig) * SW2 + nc]);
                unsigned bh1 = __float_as_uint(swh[(ka + tig + 4) * SW2 + nc]);
                unsigned bl0 = __float_as_uint(swl[(ka + tig) * SW2 + nc]);
                unsigned bl1 = __float_as_uint(swl[(ka + tig + 4) * SW2 + nc]);
                mma_tf32(acc[nt], ah0, ah1, ah2, ah3, bh0, bh1);
                mma_tf32(acc[nt], ah0, ah1, ah2, ah3, bl0, bl1);
                mma_tf32(acc[nt], al0, al1, al2, al3, bh0, bh1);
            }
        }

        __syncthreads();
#pragma unroll
        for (int nt = 0; nt < 4; nt++) {
            const int cc = nt * 8 + 2 * tig;
            *reinterpret_cast<float2*>(so + r0 * SO2 + cc)       = make_float2(acc[nt].x, acc[nt].y);
            *reinterpret_cast<float2*>(so + (r0 + 8) * SO2 + cc) = make_float2(acc[nt].z, acc[nt].w);
        }
        __syncthreads();

        for (int i = t; i < PT * 8; i += 256) {
            const int r = i >> 3, l = i & 7;
            if (r < nv)
                red_add_v4(out + (size_t)sp[r].y * COUT + l * 4,
                           *reinterpret_cast<float4*>(so + r * SO2 + l * 4));
        }
    }
}

// ---------------------------------------------------------------------------
// Inputs: feats f32[N,32], nbr_in_idx i32[K,P], nbr_out_idx i32[K,P],
// nbr_mask f32[K,P], W_in f32[K,32,64], W_out f32[K,64,32]. Output f32[N,32].
// ---------------------------------------------------------------------------
extern "C" void kernel_launch(void* const* d_in, const int* in_sizes, int n_in,
                              void* d_out, int out_size) {
    const float* feats   = (const float*)d_in[0];
    const int*   in_idx  = (const int*)  d_in[1];
    const int*   out_idx = (const int*)  d_in[2];
    const float* mask    = (const float*)d_in[3];
    const float* W_in    = (const float*)d_in[4];
    const float* W_out   = (const float*)d_in[5];
    float*       out     = (float*)      d_out;

    const int N = in_sizes[0] / CIN;
    const int K = in_sizes[4] / (CIN * CMID);
    const int P = in_sizes[3] / K;

    const int smem1 = POOL1 * (int)sizeof(float);   // ~54 KB -> 4 blocks/SM
    const int smem2 = POOL2 * (int)sizeof(float);   // ~88 KB -> 2 blocks/SM
    cudaFuncSetAttribute(fused1_kernel,
        cudaFuncAttributeMaxDynamicSharedMemorySize, smem1);
    cudaFuncSetAttribute(fused2_kernel,
        cudaFuncAttributeMaxDynamicSharedMemorySize, smem2);

    const int n_out4 = N * COUT / 4;
    const int n_h4   = N * CMID / 4;
    const int nmax   = (n_out4 > n_h4) ? n_out4 : n_h4;
    zero_kernel<<<(nmax + 255) / 256, 256>>>((float4*)out, n_out4, n_h4);

    dim3 gc((P + 255) / 256, K);
    compact_kernel<<<gc, 256>>>(in_idx, out_idx, mask, P);

    // Persistent grids sized to fill the chip (148 SMs).
    dim3 gf1(22, K);   // 594 blocks @ 4/SM
    fused1_kernel<<<gf1, 256, smem1>>>(feats, W_in);
    dim3 gf2(12, K);   // 324 blocks @ 2/SM
    fused2_kernel<<<gf2, 256, smem2>>>(W_out, out);
}

// round 10
// speedup vs baseline: 1.2733x; 1.2733x over previous
#include <cuda_runtime.h>
#include <cstdint>

// ----------------------------------------------------------------------------
// Fused sparse conv on the tensor pipe, non-persistent (one 128-pair tile per
// block — many co-resident blocks hide phase latency).
//   one memory phase: stage W hi/lo + read pair recs + gather RAW x -> smem
//   -> mma.sync.m16n8k8 tf32, 3xTF32 (x converted hi/lo at fragment load)
//   -> C tile staged into smem ALIASING x/W (single-use) -> red.v4 scatter.
// ----------------------------------------------------------------------------

constexpr int CIN   = 32;
constexpr int CMID  = 64;
constexpr int COUT  = 32;
constexpr int MAXK  = 27;
constexpr int MAXP  = 400000;
constexpr int MAXN  = 200192;
constexpr int PT    = 128;       // pairs per block

// smem strides (floats); 4 mod 32 = stride for x (r-major) covers all banks,
// 8 mod 32 for W rows; C strides multiple of 4 for float4.
constexpr int SX1 = 36;   // layer1 raw x [128][36]
constexpr int SW1 = 72;   // layer1 W planes [32][72] x2
constexpr int SO1 = 68;   // layer1 C tile [128][68]
constexpr int SX2 = 68;   // layer2 raw x [128][68]
constexpr int SW2 = 40;   // layer2 W planes [64][40] x2
constexpr int SO2 = 36;   // layer2 C tile [128][36]

constexpr int POOL1F = (PT * SX1 + 2 * CIN * SW1 > PT * SO1)
                     ?  PT * SX1 + 2 * CIN * SW1 : PT * SO1;    // 9216 f = 36 KB
constexpr int POOL2F = (PT * SX2 + 2 * CMID * SW2 > PT * SO2)
                     ?  PT * SX2 + 2 * CMID * SW2 : PT * SO2;   // 13824 f = 54 KB

__device__ float g_h[(size_t)MAXN * CMID];
__device__ uint2 g_pairs[(size_t)MAXK * MAXP];
__device__ int   g_cnt[MAXK];

static __device__ __forceinline__ unsigned f2tf(float x) {
    unsigned r; asm("cvt.rna.tf32.f32 %0, %1;" : "=r"(r) : "f"(x)); return r;
}
static __device__ __forceinline__ void hilo(float x, float& h, float& l) {
    h = __uint_as_float(f2tf(x));
    l = __uint_as_float(f2tf(x - h));
}
// on-the-fly hi/lo for A fragments
static __device__ __forceinline__ void hilo_u(float x, unsigned& h, unsigned& l) {
    h = f2tf(x);
    l = f2tf(x - __uint_as_float(h));
}
static __device__ __forceinline__ void mma_tf32(
    float4& c, unsigned a0, unsigned a1, unsigned a2, unsigned a3,
    unsigned b0, unsigned b1)
{
    asm volatile(
        "mma.sync.aligned.m16n8k8.row.col.f32.tf32.tf32.f32 "
        "{%0,%1,%2,%3}, {%4,%5,%6,%7}, {%8,%9}, {%0,%1,%2,%3};"
        : "+f"(c.x), "+f"(c.y), "+f"(c.z), "+f"(c.w)
        : "r"(a0), "r"(a1), "r"(a2), "r"(a3), "r"(b0), "r"(b1));
}
static __device__ __forceinline__ void red_add_v4(float* p, float4 v) {
    asm volatile("red.global.add.v4.f32 [%0], {%1, %2, %3, %4};"
                 :: "l"(p), "f"(v.x), "f"(v.y), "f"(v.z), "f"(v.w) : "memory");
}

// ---------------------------------------------------------------------------
__global__ void zero_kernel(float4* __restrict__ out, int n_out4, int n_h4) {
    int i = blockIdx.x * blockDim.x + threadIdx.x;
    float4 z = make_float4(0.f, 0.f, 0.f, 0.f);
    if (i < n_out4) out[i] = z;
    if (i < n_h4) reinterpret_cast<float4*>(g_h)[i] = z;
    if (i < MAXK) g_cnt[i] = 0;
}

// ---------------------------------------------------------------------------
__global__ __launch_bounds__(256) void compact_kernel(
    const int* __restrict__ in_idx, const int* __restrict__ out_idx,
    const float* __restrict__ mask, int P)
{
    const int k = blockIdx.y;
    const int p = blockIdx.x * blockDim.x + threadIdx.x;
    bool v = false; int vin = 0, vout = 0;
    if (p < P) {
        size_t o = (size_t)k * P + p;
        v = mask[o] > 0.5f;
        if (v) { vin = in_idx[o]; vout = out_idx[o]; }
    }
    unsigned b = __ballot_sync(0xffffffffu, v);
    int cnt = __popc(b);
    if (cnt == 0) return;
    const int lane = threadIdx.x & 31;
    const int leader = __ffs(b) - 1;
    int base = 0;
    if (lane == leader) base = atomicAdd(&g_cnt[k], cnt);
    base = __shfl_sync(0xffffffffu, base, leader);
    if (v) {
        int off = __popc(b & ((1u << lane) - 1u));
        g_pairs[(size_t)k * MAXP + base + off] =
            make_uint2((unsigned)vin, (unsigned)vout);
    }
}

// ---------------------------------------------------------------------------
// Fused layer 1: g_h[vout][0:64] += feats[vin][0:32] @ W_in[k]
// ---------------------------------------------------------------------------
__global__ __launch_bounds__(256) void fused1_kernel(
    const float* __restrict__ feats, const float* __restrict__ W_in)
{
    const int k    = blockIdx.y;
    const int cnt  = g_cnt[k];
    const int base = blockIdx.x * PT;
    if (base >= cnt) return;
    const int t    = threadIdx.x;
    const int lane = t & 31;
    const int wrp  = t >> 5;
    const int nv   = min(PT, cnt - base);

    extern __shared__ float pool[];
    float* sx  = pool;                   // [PT][SX1] raw x
    float* swh = pool + PT * SX1;        // [CIN][SW1]
    float* swl = swh + CIN * SW1;
    float* so  = pool;                   // C tile, aliases x+W (single-use)
    __shared__ uint2 sp[PT];

    // ---- single memory phase: W staging || pair reads || x gather ----
    {
        const int r = t >> 1, half = t & 1;
        uint2 pr = (r < nv) ? g_pairs[(size_t)k * MAXP + base + r]
                            : make_uint2(0u, 0u);
        if (half == 0) sp[r] = pr;
        const float4* src = reinterpret_cast<const float4*>(feats + (size_t)pr.x * CIN);
        float* drow = sx + r * SX1;
#pragma unroll
        for (int q = 0; q < 4; q++) {
            float4 v = src[half * 4 + q];
            float* d = drow + (half * 4 + q) * 4;
            d[0] = v.x; d[1] = v.y; d[2] = v.z; d[3] = v.w;
        }
    }
    for (int i = t; i < CIN * CMID; i += 256) {
        int c = i >> 6, d = i & 63;
        float h, l; hilo(W_in[(size_t)k * CIN * CMID + i], h, l);
        swh[c * SW1 + d] = h; swl[c * SW1 + d] = l;
    }
    __syncthreads();

    const int gid = lane >> 2, tig = lane & 3;
    const int r0  = 16 * wrp + gid;

    float4 acc[8];
#pragma unroll
    for (int nt = 0; nt < 8; nt++) acc[nt] = make_float4(0.f, 0.f, 0.f, 0.f);

#pragma unroll
    for (int ks = 0; ks < 4; ks++) {
        const int ka = ks * 8;
        unsigned ah0, al0, ah1, al1, ah2, al2, ah3, al3;
        hilo_u(sx[r0 * SX1 + ka + tig],            ah0, al0);
        hilo_u(sx[(r0 + 8) * SX1 + ka + tig],      ah1, al1);
        hilo_u(sx[r0 * SX1 + ka + tig + 4],        ah2, al2);
        hilo_u(sx[(r0 + 8) * SX1 + ka + tig + 4],  ah3, al3);
#pragma unroll
        for (int nt = 0; nt < 8; nt++) {
            const int nc = nt * 8 + gid;
            unsigned bh0 = __float_as_uint(swh[(ka + tig) * SW1 + nc]);
            unsigned bh1 = __float_as_uint(swh[(ka + tig + 4) * SW1 + nc]);
            unsigned bl0 = __float_as_uint(swl[(ka + tig) * SW1 + nc]);
            unsigned bl1 = __float_as_uint(swl[(ka + tig + 4) * SW1 + nc]);
            mma_tf32(acc[nt], ah0, ah1, ah2, ah3, bh0, bh1);
            mma_tf32(acc[nt], ah0, ah1, ah2, ah3, bl0, bl1);
            mma_tf32(acc[nt], al0, al1, al2, al3, bh0, bh1);
        }
    }

    __syncthreads();   // all reads of sx/sw done -> so may overwrite
#pragma unroll
    for (int nt = 0; nt < 8; nt++) {
        const int cc = nt * 8 + 2 * tig;
        *reinterpret_cast<float2*>(so + r0 * SO1 + cc)       = make_float2(acc[nt].x, acc[nt].y);
        *reinterpret_cast<float2*>(so + (r0 + 8) * SO1 + cc) = make_float2(acc[nt].z, acc[nt].w);
    }
    __syncthreads();

    for (int i = t; i < PT * 16; i += 256) {
        const int r = i >> 4, l = i & 15;
        if (r < nv)
            red_add_v4(g_h + (size_t)sp[r].y * CMID + l * 4,
                       *reinterpret_cast<float4*>(so + r * SO1 + l * 4));
    }
}

// ---------------------------------------------------------------------------
// Fused layer 2: out[vout][0:32] += relu(g_h[vin][0:64]) @ W_out[k]
// ---------------------------------------------------------------------------
__global__ __launch_bounds__(256) void fused2_kernel(
    const float* __restrict__ W_out, float* __restrict__ out)
{
    const int k    = blockIdx.y;
    const int cnt  = g_cnt[k];
    const int base = blockIdx.x * PT;
    if (base >= cnt) return;
    const int t    = threadIdx.x;
    const int lane = t & 31;
    const int wrp  = t >> 5;
    const int nv   = min(PT, cnt - base);

    extern __shared__ float pool[];
    float* sx  = pool;                   // [PT][SX2] raw relu(h)
    float* swh = pool + PT * SX2;        // [CMID][SW2]
    float* swl = swh + CMID * SW2;
    float* so  = pool;                   // C tile, aliases
    __shared__ uint2 sp[PT];

    // ---- single memory phase ----
    {
        const int r = t >> 1, half = t & 1;
        uint2 pr = (r < nv) ? g_pairs[(size_t)k * MAXP + base + r]
                            : make_uint2(0u, 0u);
        if (half == 0) sp[r] = pr;
        const float4* src = reinterpret_cast<const float4*>(g_h + (size_t)pr.x * CMID);
        float* drow = sx + r * SX2;
#pragma unroll
        for (int q = 0; q < 8; q++) {
            float4 v = src[half * 8 + q];
            float* d = drow + (half * 8 + q) * 4;
            d[0] = fmaxf(v.x, 0.f); d[1] = fmaxf(v.y, 0.f);
            d[2] = fmaxf(v.z, 0.f); d[3] = fmaxf(v.w, 0.f);
        }
    }
    for (int i = t; i < CMID * COUT; i += 256) {
        int c = i >> 5, d = i & 31;
        float h, l; hilo(W_out[(size_t)k * CMID * COUT + i], h, l);
        swh[c * SW2 + d] = h; swl[c * SW2 + d] = l;
    }
    __syncthreads();

    const int gid = lane >> 2, tig = lane & 3;
    const int r0  = 16 * wrp + gid;

    float4 acc[4];
#pragma unroll
    for (int nt = 0; nt < 4; nt++) acc[nt] = make_float4(0.f, 0.f, 0.f, 0.f);

#pragma unroll
    for (int ks = 0; ks < 8; ks++) {
        const int ka = ks * 8;
        unsigned ah0, al0, ah1, al1, ah2, al2, ah3, al3;
        hilo_u(sx[r0 * SX2 + ka + tig],            ah0, al0);
        hilo_u(sx[(r0 + 8) * SX2 + ka + tig],      ah1, al1);
        hilo_u(sx[r0 * SX2 + ka + tig + 4],        ah2, al2);
        hilo_u(sx[(r0 + 8) * SX2 + ka + tig + 4],  ah3, al3);
#pragma unroll
        for (int nt = 0; nt < 4; nt++) {
            const int nc = nt * 8 + gid;
            unsigned bh0 = __float_as_uint(swh[(ka + tig) * SW2 + nc]);
            unsigned bh1 = __float_as_uint(swh[(ka + tig + 4) * SW2 + nc]);
            unsigned bl0 = __float_as_uint(swl[(ka + tig) * SW2 + nc]);
            unsigned bl1 = __float_as_uint(swl[(ka + tig + 4) * SW2 + nc]);
            mma_tf32(acc[nt], ah0, ah1, ah2, ah3, bh0, bh1);
            mma_tf32(acc[nt], ah0, ah1, ah2, ah3, bl0, bl1);
            mma_tf32(acc[nt], al0, al1, al2, al3, bh0, bh1);
        }
    }

    __syncthreads();
#pragma unroll
    for (int nt = 0; nt < 4; nt++) {
        const int cc = nt * 8 + 2 * tig;
        *reinterpret_cast<float2*>(so + r0 * SO2 + cc)       = make_float2(acc[nt].x, acc[nt].y);
        *reinterpret_cast<float2*>(so + (r0 + 8) * SO2 + cc) = make_float2(acc[nt].z, acc[nt].w);
    }
    __syncthreads();

    for (int i = t; i < PT * 8; i += 256) {
        const int r = i >> 3, l = i & 7;
        if (r < nv)
            red_add_v4(out + (size_t)sp[r].y * COUT + l * 4,
                       *reinterpret_cast<float4*>(so + r * SO2 + l * 4));
    }
}

// ---------------------------------------------------------------------------
// Inputs: feats f32[N,32], nbr_in_idx i32[K,P], nbr_out_idx i32[K,P],
// nbr_mask f32[K,P], W_in f32[K,32,64], W_out f32[K,64,32]. Output f32[N,32].
// ---------------------------------------------------------------------------
extern "C" void kernel_launch(void* const* d_in, const int* in_sizes, int n_in,
                              void* d_out, int out_size) {
    const float* feats   = (const float*)d_in[0];
    const int*   in_idx  = (const int*)  d_in[1];
    const int*   out_idx = (const int*)  d_in[2];
    const float* mask    = (const float*)d_in[3];
    const float* W_in    = (const float*)d_in[4];
    const float* W_out   = (const float*)d_in[5];
    float*       out     = (float*)      d_out;

    const int N = in_sizes[0] / CIN;
    const int K = in_sizes[4] / (CIN * CMID);
    const int P = in_sizes[3] / K;

    const int smem1 = POOL1F * (int)sizeof(float);   // 36 KB
    const int smem2 = POOL2F * (int)sizeof(float);   // 54 KB
    cudaFuncSetAttribute(fused1_kernel,
        cudaFuncAttributeMaxDynamicSharedMemorySize, smem1);
    cudaFuncSetAttribute(fused2_kernel,
        cudaFuncAttributeMaxDynamicSharedMemorySize, smem2);

    const int n_out4 = N * COUT / 4;
    const int n_h4   = N * CMID / 4;
    const int nmax   = (n_out4 > n_h4) ? n_out4 : n_h4;
    zero_kernel<<<(nmax + 255) / 256, 256>>>((float4*)out, n_out4, n_h4);

    dim3 gc((P + 255) / 256, K);
    compact_kernel<<<gc, 256>>>(in_idx, out_idx, mask, P);

    dim3 gf((P + PT - 1) / PT, K);
    fused1_kernel<<<gf, 256, smem1>>>(feats, W_in);
    fused2_kernel<<<gf, 256, smem2>>>(W_out, out);
}